// round 2
// baseline (speedup 1.0000x reference)
#include <cuda_runtime.h>
#include <cstdint>
#include <cstddef>

typedef unsigned long long ull;

#define BATCH 8
#define NTOK  4096
#define DIM   64
#define BM    128
#define BN    64
#define KITER (NTOK / BN)
#define AT    128     // attention kernel threads
#define PT    192     // prep kernel threads

// ---------------- device scratch (no allocations allowed) ----------------
__device__ float    g_v [BATCH * NTOK * DIM];   // out = X@W, [b][n][d]
__device__ float    g_qt[BATCH * DIM * NTOK];   // q transposed [b][d][n]
__device__ float    g_kt[BATCH * DIM * NTOK];   // k transposed [b][d][n]
__device__ unsigned g_adjb[NTOK * (NTOK / 32)]; // adjacency bitmask (+self loops)

// ---------------- packed fp32x2 helpers (full-rate fp32 on sm_103a) ------
__device__ __forceinline__ ull pack2(float lo, float hi) {
    ull r;
    asm("mov.b64 %0, {%1, %2};" : "=l"(r) : "f"(lo), "f"(hi));
    return r;
}
__device__ __forceinline__ void unpack2(ull v, float& lo, float& hi) {
    asm("mov.b64 {%0, %1}, %2;" : "=f"(lo), "=f"(hi) : "l"(v));
}
__device__ __forceinline__ void fma2(ull& d, ull a, ull b) {
    asm("fma.rn.f32x2 %0, %1, %2, %0;" : "+l"(d) : "l"(a), "l"(b));
}
__device__ __forceinline__ void mul2(ull& d, ull s) {
    asm("mul.rn.f32x2 %0, %0, %1;" : "+l"(d) : "l"(s));
}

// ---------------- adjacency bit-pack kernel ------------------------------
__global__ void pack_adj_kernel(const int* __restrict__ A) {
    int idx = blockIdx.x * blockDim.x + threadIdx.x;  // over NTOK * 128 words
    if (idx >= NTOK * (NTOK / 32)) return;
    int row = idx >> 7;       // / 128
    int w   = idx & 127;
    const int* ap = A + (size_t)row * NTOK + w * 32;
    unsigned bits = 0u;
#pragma unroll
    for (int j = 0; j < 32; j++)
        if (ap[j] > 0) bits |= (1u << j);
    int d = row - w * 32;     // self loop
    if (d >= 0 && d < 32) bits |= (1u << d);
    g_adjb[idx] = bits;
}

// ---------------- projection kernel: v = X@W, q = X@Q, k = X@K -----------
// 64 rows per block; writes q,k TRANSPOSED to [b][d][n].
#define XS_STR 68
#define PREP_SMEM_FLOATS (64 * XS_STR + 64 * 192)
#define PREP_SMEM_BYTES  (PREP_SMEM_FLOATS * 4)

__global__ __launch_bounds__(PT) void prep_kernel(
    const float* __restrict__ X, const float* __restrict__ W,
    const float* __restrict__ Q, const float* __restrict__ Kp)
{
    extern __shared__ float sm[];
    float* xs = sm;                 // [64][XS_STR] X tile transposed [d][r]; reused as staging
    float* ws = sm + 64 * XS_STR;   // [64][192]   cols 0-63:W, 64-127:Q, 128-191:K
    const int tid = threadIdx.x;
    const int g0  = blockIdx.x * 64;       // global row (b*N + n)
    const int b   = g0 >> 12;
    const int n0  = g0 & (NTOK - 1);

    // load X tile (transpose into smem)
    for (int idx = tid; idx < 64 * 16; idx += PT) {
        int r = idx >> 4, d4 = (idx & 15) << 2;
        float4 v = *(const float4*)(X + ((size_t)(g0 + r) << 6) + d4);
        xs[(d4 + 0) * XS_STR + r] = v.x;
        xs[(d4 + 1) * XS_STR + r] = v.y;
        xs[(d4 + 2) * XS_STR + r] = v.z;
        xs[(d4 + 3) * XS_STR + r] = v.w;
    }
    // load concatenated weights
    for (int idx = tid; idx < 64 * 48; idx += PT) {
        int d = idx / 48;
        int c4 = (idx % 48) << 2;
        const float* src;
        if (c4 < 64)       src = W  + d * 64 + c4;
        else if (c4 < 128) src = Q  + d * 64 + (c4 - 64);
        else               src = Kp + d * 64 + (c4 - 128);
        *(float4*)(ws + d * 192 + c4) = *(const float4*)src;
    }
    __syncthreads();

    const int cg = tid % 24, rg = tid / 24;  // rg 0..7 (rows), cg 0..23 (col groups)
    float acc[8][8];
#pragma unroll
    for (int i = 0; i < 8; i++)
#pragma unroll
        for (int j = 0; j < 8; j++) acc[i][j] = 0.f;

#pragma unroll 4
    for (int d = 0; d < 64; d++) {
        float4 a0 = *(const float4*)(xs + d * XS_STR + (rg << 3));
        float4 a1 = *(const float4*)(xs + d * XS_STR + (rg << 3) + 4);
        float4 w0 = *(const float4*)(ws + d * 192 + (cg << 3));
        float4 w1 = *(const float4*)(ws + d * 192 + (cg << 3) + 4);
        float a[8] = {a0.x, a0.y, a0.z, a0.w, a1.x, a1.y, a1.z, a1.w};
        float w[8] = {w0.x, w0.y, w0.z, w0.w, w1.x, w1.y, w1.z, w1.w};
#pragma unroll
        for (int i = 0; i < 8; i++)
#pragma unroll
            for (int j = 0; j < 8; j++) acc[i][j] += a[i] * w[j];
    }

    // v part: direct coalesced store [b][n][d]
    if (cg < 8) {
#pragma unroll
        for (int i = 0; i < 8; i++) {
            float* dst = g_v + ((size_t)(g0 + (rg << 3) + i) << 6) + (cg << 3);
            *(float4*)(dst)     = make_float4(acc[i][0], acc[i][1], acc[i][2], acc[i][3]);
            *(float4*)(dst + 4) = make_float4(acc[i][4], acc[i][5], acc[i][6], acc[i][7]);
        }
    }

    // q part: stage transposed [oc][r] into xs region, then coalesced STG
    __syncthreads();
    if (cg >= 8 && cg < 16) {
        int oc0 = (cg - 8) << 3;
#pragma unroll
        for (int j = 0; j < 8; j++)
#pragma unroll
            for (int i = 0; i < 8; i++)
                xs[(oc0 + j) * XS_STR + (rg << 3) + i] = acc[i][j];
    }
    __syncthreads();
    for (int idx = tid; idx < 4096; idx += PT) {
        int oc = idx >> 6, r = idx & 63;
        g_qt[((size_t)(b * 64 + oc) << 12) + n0 + r] = xs[oc * XS_STR + r];
    }
    __syncthreads();
    // k part
    if (cg >= 16) {
        int oc0 = (cg - 16) << 3;
#pragma unroll
        for (int j = 0; j < 8; j++)
#pragma unroll
            for (int i = 0; i < 8; i++)
                xs[(oc0 + j) * XS_STR + (rg << 3) + i] = acc[i][j];
    }
    __syncthreads();
    for (int idx = tid; idx < 4096; idx += PT) {
        int oc = idx >> 6, r = idx & 63;
        g_kt[((size_t)(b * 64 + oc) << 12) + n0 + r] = xs[oc * XS_STR + r];
    }
}

// ---------------- fused flash-attention GAT kernel -----------------------
#define QS_OFF 0
#define KS_OFF 8192
#define VS_OFF 12288
#define PS_OFF 16384
#define PS_STR 132
#define ADJ_OFF (PS_OFF + 64 * PS_STR)            // 24832 (floats)
#define ATTN_SMEM_FLOATS (ADJ_OFF + 256)
#define ATTN_SMEM_BYTES  (ATTN_SMEM_FLOATS * 4)   // 100352

__global__ __launch_bounds__(AT, 2) void attn_kernel(float* __restrict__ out) {
    extern __shared__ float sm[];
    float*    qs   = sm + QS_OFF;                  // [d][r]  64 x 128
    float*    ks   = sm + KS_OFF;                  // [d][c]  64 x 64
    float*    vs   = sm + VS_OFF;                  // [j][oc] 64 x 64
    float*    ps   = sm + PS_OFF;                  // [j][r]  64 x PS_STR
    unsigned* adjs = (unsigned*)(sm + ADJ_OFF);    // [r][2]

    const int tid = threadIdx.x;
    const int q0  = blockIdx.x * BM;
    const int b   = blockIdx.y;
    const int rg  = tid >> 3;   // 0..15 -> 8 query rows each
    const int cg  = tid & 7;    // 0..7  -> 8 key/out cols each

    const float* qtb = g_qt + ((size_t)b << 18);
    const float* ktb = g_kt + ((size_t)b << 18);
    const float* vb  = g_v  + ((size_t)b << 18);

    // load q tile [d][r] (coalesced, pre-transposed in global)
    for (int idx = tid; idx < 64 * 32; idx += AT) {
        int d = idx >> 5, c4 = (idx & 31) << 2;
        *(float4*)(qs + d * BM + c4) = *(const float4*)(qtb + ((size_t)d << 12) + q0 + c4);
    }

    ull O2[8][4];
    float m[8], l[8];
#pragma unroll
    for (int i = 0; i < 8; i++) {
        m[i] = -INFINITY; l[i] = 0.f;
#pragma unroll
        for (int jp = 0; jp < 4; jp++) O2[i][jp] = 0ull;
    }

    for (int kt = 0; kt < KITER; kt++) {
        const int k0 = kt * BN;
        __syncthreads();   // previous PV done reading ks/vs/ps; also covers q load on iter 0
        // load k tile [d][c]
        for (int idx = tid; idx < 64 * 16; idx += AT) {
            int d = idx >> 4, c4 = (idx & 15) << 2;
            *(float4*)(ks + d * BN + c4) = *(const float4*)(ktb + ((size_t)d << 12) + k0 + c4);
        }
        // load v tile [j][oc]
        for (int idx = tid; idx < 64 * 16; idx += AT) {
            int r = idx >> 4, c4 = (idx & 15) << 2;
            *(float4*)(vs + r * DIM + c4) = *(const float4*)(vb + ((size_t)(k0 + r) << 6) + c4);
        }
        // load adjacency bits: 128 rows x 2 words
        {
            const unsigned* ab = g_adjb + (((size_t)(q0 + tid)) << 7) + (k0 >> 5);
            adjs[tid * 2]     = ab[0];
            adjs[tid * 2 + 1] = ab[1];
        }
        __syncthreads();

        // ---- S = q . k^T  (8x8 per thread, packed fp32x2) ----
        ull acc[8][4];
#pragma unroll
        for (int i = 0; i < 8; i++)
#pragma unroll
            for (int jp = 0; jp < 4; jp++) acc[i][jp] = 0ull;

#pragma unroll 4
        for (int d = 0; d < DIM; d++) {
            const float* qrow = qs + d * BM + (rg << 3);
            float4 qa = *(const float4*)(qrow);
            float4 qb = *(const float4*)(qrow + 4);
            const float* krow = ks + d * BN + (cg << 3);
            ulonglong2 ka = *(const ulonglong2*)(krow);
            ulonglong2 kb = *(const ulonglong2*)(krow + 4);
            float qv[8] = {qa.x, qa.y, qa.z, qa.w, qb.x, qb.y, qb.z, qb.w};
#pragma unroll
            for (int i = 0; i < 8; i++) {
                ull aq = pack2(qv[i], qv[i]);
                fma2(acc[i][0], aq, ka.x);
                fma2(acc[i][1], aq, ka.y);
                fma2(acc[i][2], aq, kb.x);
                fma2(acc[i][3], aq, kb.y);
            }
        }

        // ---- leaky relu + mask + online softmax ----
        float pst[8][8];   // [j][i] for contiguous transposed smem stores
#pragma unroll
        for (int i = 0; i < 8; i++) {
            float s[8];
            unpack2(acc[i][0], s[0], s[1]);
            unpack2(acc[i][1], s[2], s[3]);
            unpack2(acc[i][2], s[4], s[5]);
            unpack2(acc[i][3], s[6], s[7]);
#pragma unroll
            for (int j = 0; j < 8; j++) s[j] = s[j] > 0.f ? s[j] : 0.01f * s[j];

            unsigned w = adjs[((rg << 3) + i) * 2 + (cg >> 2)];
            const int cb = (cg << 3) & 31;
            bool val[8];
            float mloc = -INFINITY;
#pragma unroll
            for (int j = 0; j < 8; j++) {
                val[j] = (w >> (cb + j)) & 1u;
                mloc = fmaxf(mloc, val[j] ? s[j] : -INFINITY);
            }
            mloc = fmaxf(mloc, __shfl_xor_sync(0xffffffffu, mloc, 1));
            mloc = fmaxf(mloc, __shfl_xor_sync(0xffffffffu, mloc, 2));
            mloc = fmaxf(mloc, __shfl_xor_sync(0xffffffffu, mloc, 4));

            float mnew = fmaxf(m[i], mloc);
            float sc = (mnew == -INFINITY) ? 0.f : __expf(m[i] - mnew);
            float rs = 0.f;
#pragma unroll
            for (int j = 0; j < 8; j++) {
                float p = val[j] ? __expf(s[j] - mnew) : 0.f;
                pst[j][i] = p;
                rs += p;
            }
            rs += __shfl_xor_sync(0xffffffffu, rs, 1);
            rs += __shfl_xor_sync(0xffffffffu, rs, 2);
            rs += __shfl_xor_sync(0xffffffffu, rs, 4);
            l[i] = l[i] * sc + rs;
            m[i] = mnew;
            ull sc2 = pack2(sc, sc);
#pragma unroll
            for (int jp = 0; jp < 4; jp++) mul2(O2[i][jp], sc2);
        }

        // store P transposed [kcol][qrow]
#pragma unroll
        for (int j = 0; j < 8; j++) {
            float* pd = ps + ((cg << 3) + j) * PS_STR + (rg << 3);
            *(float4*)(pd)     = make_float4(pst[j][0], pst[j][1], pst[j][2], pst[j][3]);
            *(float4*)(pd + 4) = make_float4(pst[j][4], pst[j][5], pst[j][6], pst[j][7]);
        }
        __syncthreads();

        // ---- O += P @ V  (packed fp32x2) ----
#pragma unroll 4
        for (int j = 0; j < BN; j++) {
            const float* prow = ps + j * PS_STR + (rg << 3);
            float4 pa = *(const float4*)(prow);
            float4 pb = *(const float4*)(prow + 4);
            const float* vrow = vs + j * DIM + (cg << 3);
            ulonglong2 va  = *(const ulonglong2*)(vrow);
            ulonglong2 vbb = *(const ulonglong2*)(vrow + 4);
            float pv[8] = {pa.x, pa.y, pa.z, pa.w, pb.x, pb.y, pb.z, pb.w};
#pragma unroll
            for (int i = 0; i < 8; i++) {
                ull pd = pack2(pv[i], pv[i]);
                fma2(O2[i][0], pd, va.x);
                fma2(O2[i][1], pd, va.y);
                fma2(O2[i][2], pd, vbb.x);
                fma2(O2[i][3], pd, vbb.y);
            }
        }
    }

    // ---- normalize + store ----
#pragma unroll
    for (int i = 0; i < 8; i++) {
        float inv = 1.0f / l[i];
        ull iv = pack2(inv, inv);
#pragma unroll
        for (int jp = 0; jp < 4; jp++) mul2(O2[i][jp], iv);
        float o[8];
        unpack2(O2[i][0], o[0], o[1]);
        unpack2(O2[i][1], o[2], o[3]);
        unpack2(O2[i][2], o[4], o[5]);
        unpack2(O2[i][3], o[6], o[7]);
        float* dst = out + ((size_t)(b * NTOK + q0 + (rg << 3) + i) << 6) + (cg << 3);
        *(float4*)(dst)     = make_float4(o[0], o[1], o[2], o[3]);
        *(float4*)(dst + 4) = make_float4(o[4], o[5], o[6], o[7]);
    }
}

// ---------------- launch ----------------
extern "C" void kernel_launch(void* const* d_in, const int* in_sizes, int n_in,
                              void* d_out, int out_size) {
    const float* X  = (const float*)d_in[0];
    const int*   A  = (const int*)  d_in[1];
    const float* W  = (const float*)d_in[2];
    const float* Q  = (const float*)d_in[3];
    const float* Kp = (const float*)d_in[4];
    float* out = (float*)d_out;

    cudaFuncSetAttribute(prep_kernel, cudaFuncAttributeMaxDynamicSharedMemorySize, PREP_SMEM_BYTES);
    cudaFuncSetAttribute(attn_kernel, cudaFuncAttributeMaxDynamicSharedMemorySize, ATTN_SMEM_BYTES);

    pack_adj_kernel<<<(NTOK * (NTOK / 32)) / 256, 256>>>(A);
    prep_kernel<<<(BATCH * NTOK) / 64, PT, PREP_SMEM_BYTES>>>(X, W, Q, Kp);
    attn_kernel<<<dim3(NTOK / BM, BATCH), AT, ATTN_SMEM_BYTES>>>(out);
}

// round 3
// speedup vs baseline: 1.7730x; 1.7730x over previous
#include <cuda_runtime.h>
#include <cstdint>
#include <cstddef>

typedef unsigned long long ull;

#define BATCH 8
#define NTOK  4096
#define DIM   64
#define BM    128
#define BN    64
#define KITER (NTOK / BN)
#define AT    128     // attention kernel threads
#define PT    192     // prep kernel threads

// ---------------- device scratch (no allocations allowed) ----------------
__device__ float    g_v [BATCH * NTOK * DIM];   // out = X@W, [b][n][d]
__device__ float    g_qt[BATCH * DIM * NTOK];   // q transposed [b][d][n]
__device__ float    g_kt[BATCH * DIM * NTOK];   // k transposed [b][d][n]
__device__ unsigned g_adjb[NTOK * (NTOK / 32)]; // adjacency bitmask (+self loops)

// ---------------- packed fp32x2 helpers (full-rate fp32 on sm_103a) ------
__device__ __forceinline__ ull pack2(float lo, float hi) {
    ull r;
    asm("mov.b64 %0, {%1, %2};" : "=l"(r) : "f"(lo), "f"(hi));
    return r;
}
__device__ __forceinline__ void unpack2(ull v, float& lo, float& hi) {
    asm("mov.b64 {%0, %1}, %2;" : "=f"(lo), "=f"(hi) : "l"(v));
}
__device__ __forceinline__ void fma2(ull& d, ull a, ull b) {
    asm("fma.rn.f32x2 %0, %1, %2, %0;" : "+l"(d) : "l"(a), "l"(b));
}
__device__ __forceinline__ void mul2(ull& d, ull s) {
    asm("mul.rn.f32x2 %0, %0, %1;" : "+l"(d) : "l"(s));
}

// ---------------- adjacency bit-pack kernel (ballot) ---------------------
// One warp packs 32 consecutive words (1024 ints); coalesced 128B reads.
__global__ void pack_adj_kernel(const int* __restrict__ A) {
    int gtid = blockIdx.x * blockDim.x + threadIdx.x;
    int gw   = gtid >> 5;          // global warp id
    int lane = gtid & 31;
    int wb   = gw * 32;            // first word this warp produces
    if (wb >= NTOK * (NTOK / 32)) return;
    int row   = wb >> 7;           // 128 words per row; 32 | 128 so no row crossing
    int wcol0 = wb & 127;
    const int* ap = A + (size_t)row * NTOK + wcol0 * 32;
    unsigned mine = 0u;
#pragma unroll 8
    for (int k = 0; k < 32; k++) {
        unsigned b = __ballot_sync(0xffffffffu, ap[k * 32 + lane] > 0);
        if (lane == k) mine = b;
    }
    // self loop
    if (wcol0 + lane == (row >> 5)) mine |= 1u << (row & 31);
    g_adjb[wb + lane] = mine;
}

// ---------------- projection kernel: v = X@W, q = X@Q, k = X@K -----------
// 64 rows per block; writes q,k TRANSPOSED to [b][d][n].
#define XS_STR 68
#define PREP_SMEM_FLOATS (64 * XS_STR + 64 * 192)
#define PREP_SMEM_BYTES  (PREP_SMEM_FLOATS * 4)

__global__ __launch_bounds__(PT) void prep_kernel(
    const float* __restrict__ X, const float* __restrict__ W,
    const float* __restrict__ Q, const float* __restrict__ Kp)
{
    extern __shared__ float sm[];
    float* xs = sm;                 // [64][XS_STR] X tile transposed [d][r]; reused as staging
    float* ws = sm + 64 * XS_STR;   // [64][192]   cols 0-63:W, 64-127:Q, 128-191:K
    const int tid = threadIdx.x;
    const int g0  = blockIdx.x * 64;       // global row (b*N + n)
    const int b   = g0 >> 12;
    const int n0  = g0 & (NTOK - 1);

    for (int idx = tid; idx < 64 * 16; idx += PT) {
        int r = idx >> 4, d4 = (idx & 15) << 2;
        float4 v = *(const float4*)(X + ((size_t)(g0 + r) << 6) + d4);
        xs[(d4 + 0) * XS_STR + r] = v.x;
        xs[(d4 + 1) * XS_STR + r] = v.y;
        xs[(d4 + 2) * XS_STR + r] = v.z;
        xs[(d4 + 3) * XS_STR + r] = v.w;
    }
    for (int idx = tid; idx < 64 * 48; idx += PT) {
        int d = idx / 48;
        int c4 = (idx % 48) << 2;
        const float* src;
        if (c4 < 64)       src = W  + d * 64 + c4;
        else if (c4 < 128) src = Q  + d * 64 + (c4 - 64);
        else               src = Kp + d * 64 + (c4 - 128);
        *(float4*)(ws + d * 192 + c4) = *(const float4*)src;
    }
    __syncthreads();

    const int cg = tid % 24, rg = tid / 24;
    float acc[8][8];
#pragma unroll
    for (int i = 0; i < 8; i++)
#pragma unroll
        for (int j = 0; j < 8; j++) acc[i][j] = 0.f;

#pragma unroll 4
    for (int d = 0; d < 64; d++) {
        float4 a0 = *(const float4*)(xs + d * XS_STR + (rg << 3));
        float4 a1 = *(const float4*)(xs + d * XS_STR + (rg << 3) + 4);
        float4 w0 = *(const float4*)(ws + d * 192 + (cg << 3));
        float4 w1 = *(const float4*)(ws + d * 192 + (cg << 3) + 4);
        float a[8] = {a0.x, a0.y, a0.z, a0.w, a1.x, a1.y, a1.z, a1.w};
        float w[8] = {w0.x, w0.y, w0.z, w0.w, w1.x, w1.y, w1.z, w1.w};
#pragma unroll
        for (int i = 0; i < 8; i++)
#pragma unroll
            for (int j = 0; j < 8; j++) acc[i][j] += a[i] * w[j];
    }

    if (cg < 8) {
#pragma unroll
        for (int i = 0; i < 8; i++) {
            float* dst = g_v + ((size_t)(g0 + (rg << 3) + i) << 6) + (cg << 3);
            *(float4*)(dst)     = make_float4(acc[i][0], acc[i][1], acc[i][2], acc[i][3]);
            *(float4*)(dst + 4) = make_float4(acc[i][4], acc[i][5], acc[i][6], acc[i][7]);
        }
    }

    __syncthreads();
    if (cg >= 8 && cg < 16) {
        int oc0 = (cg - 8) << 3;
#pragma unroll
        for (int j = 0; j < 8; j++)
#pragma unroll
            for (int i = 0; i < 8; i++)
                xs[(oc0 + j) * XS_STR + (rg << 3) + i] = acc[i][j];
    }
    __syncthreads();
    for (int idx = tid; idx < 4096; idx += PT) {
        int oc = idx >> 6, r = idx & 63;
        g_qt[((size_t)(b * 64 + oc) << 12) + n0 + r] = xs[oc * XS_STR + r];
    }
    __syncthreads();
    if (cg >= 16) {
        int oc0 = (cg - 16) << 3;
#pragma unroll
        for (int j = 0; j < 8; j++)
#pragma unroll
            for (int i = 0; i < 8; i++)
                xs[(oc0 + j) * XS_STR + (rg << 3) + i] = acc[i][j];
    }
    __syncthreads();
    for (int idx = tid; idx < 4096; idx += PT) {
        int oc = idx >> 6, r = idx & 63;
        g_kt[((size_t)(b * 64 + oc) << 12) + n0 + r] = xs[oc * XS_STR + r];
    }
}

// ---------------- fused flash-attention GAT kernel -----------------------
// P is stored ROW-MAJOR [qrow][kcol], stride 68, with a 16B-chunk XOR swizzle
// (chunk ^ ((rg&3)<<1)) so both stores and loads are bank-conflict-free.
#define QS_OFF 0
#define KS_OFF 8192
#define VS_OFF 12288
#define PS_OFF 16384
#define PS_STR 68
#define ADJ_OFF (PS_OFF + 128 * PS_STR)           // 25088 floats
#define ATTN_SMEM_FLOATS (ADJ_OFF + 256)
#define ATTN_SMEM_BYTES  (ATTN_SMEM_FLOATS * 4)   // 101376

__global__ __launch_bounds__(AT, 2) void attn_kernel(float* __restrict__ out) {
    extern __shared__ float sm[];
    float*    qs   = sm + QS_OFF;                  // [d][r]  64 x 128
    float*    ks   = sm + KS_OFF;                  // [d][c]  64 x 64
    float*    vs   = sm + VS_OFF;                  // [j][oc] 64 x 64
    float*    ps   = sm + PS_OFF;                  // [row][col] 128 x 68 (swizzled chunks)
    unsigned* adjs = (unsigned*)(sm + ADJ_OFF);    // [r][2]

    const int tid = threadIdx.x;
    const int q0  = blockIdx.x * BM;
    const int b   = blockIdx.y;
    const int rg  = tid >> 3;   // 0..15 -> 8 query rows each
    const int cg  = tid & 7;    // 0..7  -> 8 key/out cols each
    const int sw  = (rg & 3) << 1;   // chunk swizzle for this thread's rows

    const float* qtb = g_qt + ((size_t)b << 18);
    const float* ktb = g_kt + ((size_t)b << 18);
    const float* vb  = g_v  + ((size_t)b << 18);

    // load q tile [d][r] (coalesced, pre-transposed in global)
    for (int idx = tid; idx < 64 * 32; idx += AT) {
        int d = idx >> 5, c4 = (idx & 31) << 2;
        *(float4*)(qs + d * BM + c4) = *(const float4*)(qtb + ((size_t)d << 12) + q0 + c4);
    }

    ull O2[8][4];
    float m[8], l[8];
#pragma unroll
    for (int i = 0; i < 8; i++) {
        m[i] = -INFINITY; l[i] = 0.f;
#pragma unroll
        for (int jp = 0; jp < 4; jp++) O2[i][jp] = 0ull;
    }

    for (int kt = 0; kt < KITER; kt++) {
        const int k0 = kt * BN;
        __syncthreads();   // previous PV done reading ks/vs; also covers q load on iter 0
        // load k tile [d][c]
        for (int idx = tid; idx < 64 * 16; idx += AT) {
            int d = idx >> 4, c4 = (idx & 15) << 2;
            *(float4*)(ks + d * BN + c4) = *(const float4*)(ktb + ((size_t)d << 12) + k0 + c4);
        }
        // load v tile [j][oc]
        for (int idx = tid; idx < 64 * 16; idx += AT) {
            int r = idx >> 4, c4 = (idx & 15) << 2;
            *(float4*)(vs + r * DIM + c4) = *(const float4*)(vb + ((size_t)(k0 + r) << 6) + c4);
        }
        // adjacency bits: 128 rows x 2 words (8B-aligned -> uint2)
        {
            const uint2* ab = (const uint2*)(g_adjb + (((size_t)(q0 + tid)) << 7) + (k0 >> 5));
            *(uint2*)(adjs + tid * 2) = *ab;
        }
        __syncthreads();

        // ---- S = q . k^T  (8x8 per thread, packed fp32x2) ----
        ull acc[8][4];
#pragma unroll
        for (int i = 0; i < 8; i++)
#pragma unroll
            for (int jp = 0; jp < 4; jp++) acc[i][jp] = 0ull;

#pragma unroll 4
        for (int d = 0; d < DIM; d++) {
            const float* qrow = qs + d * BM + (rg << 3);
            float4 qa = *(const float4*)(qrow);
            float4 qb = *(const float4*)(qrow + 4);
            const float* krow = ks + d * BN + (cg << 3);
            ulonglong2 ka = *(const ulonglong2*)(krow);
            ulonglong2 kb = *(const ulonglong2*)(krow + 4);
            float qv[8] = {qa.x, qa.y, qa.z, qa.w, qb.x, qb.y, qb.z, qb.w};
#pragma unroll
            for (int i = 0; i < 8; i++) {
                ull aq = pack2(qv[i], qv[i]);
                fma2(acc[i][0], aq, ka.x);
                fma2(acc[i][1], aq, ka.y);
                fma2(acc[i][2], aq, kb.x);
                fma2(acc[i][3], aq, kb.y);
            }
        }

        // ---- leaky relu + mask + online softmax; store P row-major -----
#pragma unroll
        for (int i = 0; i < 8; i++) {
            const int row = (rg << 3) + i;
            float s[8];
            unpack2(acc[i][0], s[0], s[1]);
            unpack2(acc[i][1], s[2], s[3]);
            unpack2(acc[i][2], s[4], s[5]);
            unpack2(acc[i][3], s[6], s[7]);
#pragma unroll
            for (int j = 0; j < 8; j++) s[j] = s[j] > 0.f ? s[j] : 0.01f * s[j];

            unsigned w = adjs[row * 2 + (cg >> 2)];
            const int cb = (cg & 3) << 3;
            bool val[8];
            float mloc = -INFINITY;
#pragma unroll
            for (int j = 0; j < 8; j++) {
                val[j] = (w >> (cb + j)) & 1u;
                mloc = fmaxf(mloc, val[j] ? s[j] : -INFINITY);
            }
            mloc = fmaxf(mloc, __shfl_xor_sync(0xffffffffu, mloc, 1));
            mloc = fmaxf(mloc, __shfl_xor_sync(0xffffffffu, mloc, 2));
            mloc = fmaxf(mloc, __shfl_xor_sync(0xffffffffu, mloc, 4));

            float mnew = fmaxf(m[i], mloc);
            float sc = (mnew == -INFINITY) ? 0.f : __expf(m[i] - mnew);
            float p[8];
            float rs = 0.f;
#pragma unroll
            for (int j = 0; j < 8; j++) {
                p[j] = val[j] ? __expf(s[j] - mnew) : 0.f;
                rs += p[j];
            }
            rs += __shfl_xor_sync(0xffffffffu, rs, 1);
            rs += __shfl_xor_sync(0xffffffffu, rs, 2);
            rs += __shfl_xor_sync(0xffffffffu, rs, 4);
            l[i] = l[i] * sc + rs;
            m[i] = mnew;
            ull sc2 = pack2(sc, sc);
#pragma unroll
            for (int jp = 0; jp < 4; jp++) mul2(O2[i][jp], sc2);

            // store this P row immediately (2 swizzled STS.128); no pst array
            float* base = ps + row * PS_STR;
            *(float4*)(base + ((((cg << 1))     ^ sw) << 2)) = make_float4(p[0], p[1], p[2], p[3]);
            *(float4*)(base + ((((cg << 1) + 1) ^ sw) << 2)) = make_float4(p[4], p[5], p[6], p[7]);
        }
        __syncthreads();

        // ---- O += P @ V  (packed fp32x2) ----
#pragma unroll 2
        for (int jb = 0; jb < 16; jb++) {
            float pr[8][4];
#pragma unroll
            for (int i = 0; i < 8; i++) {
                const int row = (rg << 3) + i;
                float4 t = *(const float4*)(ps + row * PS_STR + ((jb ^ sw) << 2));
                pr[i][0] = t.x; pr[i][1] = t.y; pr[i][2] = t.z; pr[i][3] = t.w;
            }
#pragma unroll
            for (int jj = 0; jj < 4; jj++) {
                const int j = (jb << 2) + jj;
                const float* vrow = vs + j * DIM + (cg << 3);
                ulonglong2 va  = *(const ulonglong2*)(vrow);
                ulonglong2 vbb = *(const ulonglong2*)(vrow + 4);
#pragma unroll
                for (int i = 0; i < 8; i++) {
                    ull pd = pack2(pr[i][jj], pr[i][jj]);
                    fma2(O2[i][0], pd, va.x);
                    fma2(O2[i][1], pd, va.y);
                    fma2(O2[i][2], pd, vbb.x);
                    fma2(O2[i][3], pd, vbb.y);
                }
            }
        }
    }

    // ---- normalize + store ----
#pragma unroll
    for (int i = 0; i < 8; i++) {
        float inv = 1.0f / l[i];
        ull iv = pack2(inv, inv);
#pragma unroll
        for (int jp = 0; jp < 4; jp++) mul2(O2[i][jp], iv);
        float o[8];
        unpack2(O2[i][0], o[0], o[1]);
        unpack2(O2[i][1], o[2], o[3]);
        unpack2(O2[i][2], o[4], o[5]);
        unpack2(O2[i][3], o[6], o[7]);
        float* dst = out + ((size_t)(b * NTOK + q0 + (rg << 3) + i) << 6) + (cg << 3);
        *(float4*)(dst)     = make_float4(o[0], o[1], o[2], o[3]);
        *(float4*)(dst + 4) = make_float4(o[4], o[5], o[6], o[7]);
    }
}

// ---------------- launch ----------------
extern "C" void kernel_launch(void* const* d_in, const int* in_sizes, int n_in,
                              void* d_out, int out_size) {
    const float* X  = (const float*)d_in[0];
    const int*   A  = (const int*)  d_in[1];
    const float* W  = (const float*)d_in[2];
    const float* Q  = (const float*)d_in[3];
    const float* Kp = (const float*)d_in[4];
    float* out = (float*)d_out;

    cudaFuncSetAttribute(prep_kernel, cudaFuncAttributeMaxDynamicSharedMemorySize, PREP_SMEM_BYTES);
    cudaFuncSetAttribute(attn_kernel, cudaFuncAttributeMaxDynamicSharedMemorySize, ATTN_SMEM_BYTES);

    pack_adj_kernel<<<(NTOK * (NTOK / 32)) / 256, 256>>>(A);
    prep_kernel<<<(BATCH * NTOK) / 64, PT, PREP_SMEM_BYTES>>>(X, W, Q, Kp);
    attn_kernel<<<dim3(NTOK / BM, BATCH), AT, ATTN_SMEM_BYTES>>>(out);
}

// round 4
// speedup vs baseline: 1.7834x; 1.0059x over previous
#include <cuda_runtime.h>
#include <cstdint>
#include <cstddef>

typedef unsigned long long ull;

#define BATCH 8
#define NTOK  4096
#define DIM   64
#define BM    128
#define BN    64
#define KITER (NTOK / BN)
#define AT    128     // attention kernel threads
#define PT    192     // prep kernel threads

// ---------------- device scratch (no allocations allowed) ----------------
__device__ float    g_v [BATCH * NTOK * DIM];   // out = X@W, [b][n][d]
__device__ float    g_qt[BATCH * DIM * NTOK];   // q transposed [b][d][n]
__device__ float    g_kt[BATCH * DIM * NTOK];   // k transposed [b][d][n]
__device__ unsigned g_adjb[NTOK * (NTOK / 32)]; // adjacency bitmask (+self loops)

// ---------------- packed fp32x2 helpers (full-rate fp32 on sm_103a) ------
__device__ __forceinline__ ull pack2(float lo, float hi) {
    ull r;
    asm("mov.b64 %0, {%1, %2};" : "=l"(r) : "f"(lo), "f"(hi));
    return r;
}
__device__ __forceinline__ void unpack2(ull v, float& lo, float& hi) {
    asm("mov.b64 {%0, %1}, %2;" : "=f"(lo), "=f"(hi) : "l"(v));
}
__device__ __forceinline__ void fma2(ull& d, ull a, ull b) {
    asm("fma.rn.f32x2 %0, %1, %2, %0;" : "+l"(d) : "l"(a), "l"(b));
}
__device__ __forceinline__ void mul2(ull& d, ull s) {
    asm("mul.rn.f32x2 %0, %0, %1;" : "+l"(d) : "l"(s));
}

// ---------------- adjacency bit-pack kernel (ballot) ---------------------
// One warp packs 32 consecutive words (1024 ints); coalesced 128B reads.
__global__ void pack_adj_kernel(const int* __restrict__ A) {
    int gtid = blockIdx.x * blockDim.x + threadIdx.x;
    int gw   = gtid >> 5;          // global warp id
    int lane = gtid & 31;
    int wb   = gw * 32;            // first word this warp produces
    if (wb >= NTOK * (NTOK / 32)) return;
    int row   = wb >> 7;           // 128 words per row; 32 | 128 so no row crossing
    int wcol0 = wb & 127;
    const int* ap = A + (size_t)row * NTOK + wcol0 * 32;
    unsigned mine = 0u;
#pragma unroll 8
    for (int k = 0; k < 32; k++) {
        unsigned b = __ballot_sync(0xffffffffu, ap[k * 32 + lane] > 0);
        if (lane == k) mine = b;
    }
    // self loop
    if (wcol0 + lane == (row >> 5)) mine |= 1u << (row & 31);
    g_adjb[wb + lane] = mine;
}

// ---------------- projection kernel: v = X@W, q = X@Q, k = X@K -----------
// 64 rows per block; writes q,k TRANSPOSED to [b][d][n].
#define XS_STR 68
#define PREP_SMEM_FLOATS (64 * XS_STR + 64 * 192)
#define PREP_SMEM_BYTES  (PREP_SMEM_FLOATS * 4)

__global__ __launch_bounds__(PT) void prep_kernel(
    const float* __restrict__ X, const float* __restrict__ W,
    const float* __restrict__ Q, const float* __restrict__ Kp)
{
    extern __shared__ float sm[];
    float* xs = sm;                 // [64][XS_STR] X tile transposed [d][r]; reused as staging
    float* ws = sm + 64 * XS_STR;   // [64][192]   cols 0-63:W, 64-127:Q, 128-191:K
    const int tid = threadIdx.x;
    const int g0  = blockIdx.x * 64;       // global row (b*N + n)
    const int b   = g0 >> 12;
    const int n0  = g0 & (NTOK - 1);

    for (int idx = tid; idx < 64 * 16; idx += PT) {
        int r = idx >> 4, d4 = (idx & 15) << 2;
        float4 v = *(const float4*)(X + ((size_t)(g0 + r) << 6) + d4);
        xs[(d4 + 0) * XS_STR + r] = v.x;
        xs[(d4 + 1) * XS_STR + r] = v.y;
        xs[(d4 + 2) * XS_STR + r] = v.z;
        xs[(d4 + 3) * XS_STR + r] = v.w;
    }
    for (int idx = tid; idx < 64 * 48; idx += PT) {
        int d = idx / 48;
        int c4 = (idx % 48) << 2;
        const float* src;
        if (c4 < 64)       src = W  + d * 64 + c4;
        else if (c4 < 128) src = Q  + d * 64 + (c4 - 64);
        else               src = Kp + d * 64 + (c4 - 128);
        *(float4*)(ws + d * 192 + c4) = *(const float4*)src;
    }
    __syncthreads();

    const int cg = tid % 24, rg = tid / 24;
    float acc[8][8];
#pragma unroll
    for (int i = 0; i < 8; i++)
#pragma unroll
        for (int j = 0; j < 8; j++) acc[i][j] = 0.f;

#pragma unroll 4
    for (int d = 0; d < 64; d++) {
        float4 a0 = *(const float4*)(xs + d * XS_STR + (rg << 3));
        float4 a1 = *(const float4*)(xs + d * XS_STR + (rg << 3) + 4);
        float4 w0 = *(const float4*)(ws + d * 192 + (cg << 3));
        float4 w1 = *(const float4*)(ws + d * 192 + (cg << 3) + 4);
        float a[8] = {a0.x, a0.y, a0.z, a0.w, a1.x, a1.y, a1.z, a1.w};
        float w[8] = {w0.x, w0.y, w0.z, w0.w, w1.x, w1.y, w1.z, w1.w};
#pragma unroll
        for (int i = 0; i < 8; i++)
#pragma unroll
            for (int j = 0; j < 8; j++) acc[i][j] += a[i] * w[j];
    }

    if (cg < 8) {
#pragma unroll
        for (int i = 0; i < 8; i++) {
            float* dst = g_v + ((size_t)(g0 + (rg << 3) + i) << 6) + (cg << 3);
            *(float4*)(dst)     = make_float4(acc[i][0], acc[i][1], acc[i][2], acc[i][3]);
            *(float4*)(dst + 4) = make_float4(acc[i][4], acc[i][5], acc[i][6], acc[i][7]);
        }
    }

    __syncthreads();
    if (cg >= 8 && cg < 16) {
        int oc0 = (cg - 8) << 3;
#pragma unroll
        for (int j = 0; j < 8; j++)
#pragma unroll
            for (int i = 0; i < 8; i++)
                xs[(oc0 + j) * XS_STR + (rg << 3) + i] = acc[i][j];
    }
    __syncthreads();
    for (int idx = tid; idx < 4096; idx += PT) {
        int oc = idx >> 6, r = idx & 63;
        g_qt[((size_t)(b * 64 + oc) << 12) + n0 + r] = xs[oc * XS_STR + r];
    }
    __syncthreads();
    if (cg >= 16) {
        int oc0 = (cg - 16) << 3;
#pragma unroll
        for (int j = 0; j < 8; j++)
#pragma unroll
            for (int i = 0; i < 8; i++)
                xs[(oc0 + j) * XS_STR + (rg << 3) + i] = acc[i][j];
    }
    __syncthreads();
    for (int idx = tid; idx < 4096; idx += PT) {
        int oc = idx >> 6, r = idx & 63;
        g_kt[((size_t)(b * 64 + oc) << 12) + n0 + r] = xs[oc * XS_STR + r];
    }
}

// ---------------- fused flash-attention GAT kernel -----------------------
// P is stored ROW-MAJOR [qrow][kcol], stride 68, with a 16B-chunk XOR swizzle
// (chunk ^ ((rg&3)<<1)) so both stores and loads are bank-conflict-free.
#define QS_OFF 0
#define KS_OFF 8192
#define VS_OFF 12288
#define PS_OFF 16384
#define PS_STR 68
#define ADJ_OFF (PS_OFF + 128 * PS_STR)           // 25088 floats
#define ATTN_SMEM_FLOATS (ADJ_OFF + 256)
#define ATTN_SMEM_BYTES  (ATTN_SMEM_FLOATS * 4)   // 101376

__global__ __launch_bounds__(AT, 2) void attn_kernel(float* __restrict__ out) {
    extern __shared__ float sm[];
    float*    qs   = sm + QS_OFF;                  // [d][r]  64 x 128
    float*    ks   = sm + KS_OFF;                  // [d][c]  64 x 64
    float*    vs   = sm + VS_OFF;                  // [j][oc] 64 x 64
    float*    ps   = sm + PS_OFF;                  // [row][col] 128 x 68 (swizzled chunks)
    unsigned* adjs = (unsigned*)(sm + ADJ_OFF);    // [r][2]

    const int tid = threadIdx.x;
    const int q0  = blockIdx.x * BM;
    const int b   = blockIdx.y;
    const int rg  = tid >> 3;   // 0..15 -> 8 query rows each
    const int cg  = tid & 7;    // 0..7  -> 8 key/out cols each
    const int sw  = (rg & 3) << 1;   // chunk swizzle for this thread's rows

    const float* qtb = g_qt + ((size_t)b << 18);
    const float* ktb = g_kt + ((size_t)b << 18);
    const float* vb  = g_v  + ((size_t)b << 18);

    // load q tile [d][r] (coalesced, pre-transposed in global)
    for (int idx = tid; idx < 64 * 32; idx += AT) {
        int d = idx >> 5, c4 = (idx & 31) << 2;
        *(float4*)(qs + d * BM + c4) = *(const float4*)(qtb + ((size_t)d << 12) + q0 + c4);
    }

    ull O2[8][4];
    float m[8], l[8];
#pragma unroll
    for (int i = 0; i < 8; i++) {
        m[i] = -INFINITY; l[i] = 0.f;
#pragma unroll
        for (int jp = 0; jp < 4; jp++) O2[i][jp] = 0ull;
    }

    for (int kt = 0; kt < KITER; kt++) {
        const int k0 = kt * BN;
        __syncthreads();   // previous PV done reading ks/vs; also covers q load on iter 0
        // load k tile [d][c]
        for (int idx = tid; idx < 64 * 16; idx += AT) {
            int d = idx >> 4, c4 = (idx & 15) << 2;
            *(float4*)(ks + d * BN + c4) = *(const float4*)(ktb + ((size_t)d << 12) + k0 + c4);
        }
        // load v tile [j][oc]
        for (int idx = tid; idx < 64 * 16; idx += AT) {
            int r = idx >> 4, c4 = (idx & 15) << 2;
            *(float4*)(vs + r * DIM + c4) = *(const float4*)(vb + ((size_t)(k0 + r) << 6) + c4);
        }
        // adjacency bits: 128 rows x 2 words (8B-aligned -> uint2)
        {
            const uint2* ab = (const uint2*)(g_adjb + (((size_t)(q0 + tid)) << 7) + (k0 >> 5));
            *(uint2*)(adjs + tid * 2) = *ab;
        }
        __syncthreads();

        // ---- S = q . k^T  (8x8 per thread, packed fp32x2) ----
        ull acc[8][4];
#pragma unroll
        for (int i = 0; i < 8; i++)
#pragma unroll
            for (int jp = 0; jp < 4; jp++) acc[i][jp] = 0ull;

#pragma unroll 4
        for (int d = 0; d < DIM; d++) {
            const float* qrow = qs + d * BM + (rg << 3);
            float4 qa = *(const float4*)(qrow);
            float4 qb = *(const float4*)(qrow + 4);
            const float* krow = ks + d * BN + (cg << 3);
            ulonglong2 ka = *(const ulonglong2*)(krow);
            ulonglong2 kb = *(const ulonglong2*)(krow + 4);
            float qv[8] = {qa.x, qa.y, qa.z, qa.w, qb.x, qb.y, qb.z, qb.w};
#pragma unroll
            for (int i = 0; i < 8; i++) {
                ull aq = pack2(qv[i], qv[i]);
                fma2(acc[i][0], aq, ka.x);
                fma2(acc[i][1], aq, ka.y);
                fma2(acc[i][2], aq, kb.x);
                fma2(acc[i][3], aq, kb.y);
            }
        }

        // ---- leaky relu + mask + online softmax; store P row-major -----
#pragma unroll
        for (int i = 0; i < 8; i++) {
            const int row = (rg << 3) + i;
            float s[8];
            unpack2(acc[i][0], s[0], s[1]);
            unpack2(acc[i][1], s[2], s[3]);
            unpack2(acc[i][2], s[4], s[5]);
            unpack2(acc[i][3], s[6], s[7]);
#pragma unroll
            for (int j = 0; j < 8; j++) s[j] = s[j] > 0.f ? s[j] : 0.01f * s[j];

            unsigned w = adjs[row * 2 + (cg >> 2)];
            const int cb = (cg & 3) << 3;
            bool val[8];
            float mloc = -INFINITY;
#pragma unroll
            for (int j = 0; j < 8; j++) {
                val[j] = (w >> (cb + j)) & 1u;
                mloc = fmaxf(mloc, val[j] ? s[j] : -INFINITY);
            }
            mloc = fmaxf(mloc, __shfl_xor_sync(0xffffffffu, mloc, 1));
            mloc = fmaxf(mloc, __shfl_xor_sync(0xffffffffu, mloc, 2));
            mloc = fmaxf(mloc, __shfl_xor_sync(0xffffffffu, mloc, 4));

            float mnew = fmaxf(m[i], mloc);
            float sc = (mnew == -INFINITY) ? 0.f : __expf(m[i] - mnew);
            float p[8];
            float rs = 0.f;
#pragma unroll
            for (int j = 0; j < 8; j++) {
                p[j] = val[j] ? __expf(s[j] - mnew) : 0.f;
                rs += p[j];
            }
            rs += __shfl_xor_sync(0xffffffffu, rs, 1);
            rs += __shfl_xor_sync(0xffffffffu, rs, 2);
            rs += __shfl_xor_sync(0xffffffffu, rs, 4);
            l[i] = l[i] * sc + rs;
            m[i] = mnew;
            ull sc2 = pack2(sc, sc);
#pragma unroll
            for (int jp = 0; jp < 4; jp++) mul2(O2[i][jp], sc2);

            // store this P row immediately (2 swizzled STS.128); no pst array
            float* base = ps + row * PS_STR;
            *(float4*)(base + ((((cg << 1))     ^ sw) << 2)) = make_float4(p[0], p[1], p[2], p[3]);
            *(float4*)(base + ((((cg << 1) + 1) ^ sw) << 2)) = make_float4(p[4], p[5], p[6], p[7]);
        }
        __syncthreads();

        // ---- O += P @ V  (packed fp32x2) ----
#pragma unroll 2
        for (int jb = 0; jb < 16; jb++) {
            float pr[8][4];
#pragma unroll
            for (int i = 0; i < 8; i++) {
                const int row = (rg << 3) + i;
                float4 t = *(const float4*)(ps + row * PS_STR + ((jb ^ sw) << 2));
                pr[i][0] = t.x; pr[i][1] = t.y; pr[i][2] = t.z; pr[i][3] = t.w;
            }
#pragma unroll
            for (int jj = 0; jj < 4; jj++) {
                const int j = (jb << 2) + jj;
                const float* vrow = vs + j * DIM + (cg << 3);
                ulonglong2 va  = *(const ulonglong2*)(vrow);
                ulonglong2 vbb = *(const ulonglong2*)(vrow + 4);
#pragma unroll
                for (int i = 0; i < 8; i++) {
                    ull pd = pack2(pr[i][jj], pr[i][jj]);
                    fma2(O2[i][0], pd, va.x);
                    fma2(O2[i][1], pd, va.y);
                    fma2(O2[i][2], pd, vbb.x);
                    fma2(O2[i][3], pd, vbb.y);
                }
            }
        }
    }

    // ---- normalize + store ----
#pragma unroll
    for (int i = 0; i < 8; i++) {
        float inv = 1.0f / l[i];
        ull iv = pack2(inv, inv);
#pragma unroll
        for (int jp = 0; jp < 4; jp++) mul2(O2[i][jp], iv);
        float o[8];
        unpack2(O2[i][0], o[0], o[1]);
        unpack2(O2[i][1], o[2], o[3]);
        unpack2(O2[i][2], o[4], o[5]);
        unpack2(O2[i][3], o[6], o[7]);
        float* dst = out + ((size_t)(b * NTOK + q0 + (rg << 3) + i) << 6) + (cg << 3);
        *(float4*)(dst)     = make_float4(o[0], o[1], o[2], o[3]);
        *(float4*)(dst + 4) = make_float4(o[4], o[5], o[6], o[7]);
    }
}

// ---------------- launch ----------------
extern "C" void kernel_launch(void* const* d_in, const int* in_sizes, int n_in,
                              void* d_out, int out_size) {
    const float* X  = (const float*)d_in[0];
    const int*   A  = (const int*)  d_in[1];
    const float* W  = (const float*)d_in[2];
    const float* Q  = (const float*)d_in[3];
    const float* Kp = (const float*)d_in[4];
    float* out = (float*)d_out;

    cudaFuncSetAttribute(prep_kernel, cudaFuncAttributeMaxDynamicSharedMemorySize, PREP_SMEM_BYTES);
    cudaFuncSetAttribute(attn_kernel, cudaFuncAttributeMaxDynamicSharedMemorySize, ATTN_SMEM_BYTES);

    pack_adj_kernel<<<(NTOK * (NTOK / 32)) / 256, 256>>>(A);
    prep_kernel<<<(BATCH * NTOK) / 64, PT, PREP_SMEM_BYTES>>>(X, W, Q, Kp);
    attn_kernel<<<dim3(NTOK / BM, BATCH), AT, ATTN_SMEM_BYTES>>>(out);
}

// round 5
// speedup vs baseline: 2.1931x; 1.2297x over previous
#include <cuda_runtime.h>
#include <cstdint>
#include <cstddef>

typedef unsigned long long ull;

#define BATCH 8
#define NTOK  4096
#define DIM   64
#define BM    128
#define BN    64
#define KITER (NTOK / BN)
#define AT    128     // attention kernel threads
#define PT    192     // prep kernel threads

// ---------------- device scratch (no allocations allowed) ----------------
__device__ float    g_v [BATCH * NTOK * DIM];   // out = X@W, [b][n][d]
__device__ float    g_qt[BATCH * DIM * NTOK];   // q transposed [b][d][n]
__device__ float    g_kt[BATCH * DIM * NTOK];   // k transposed [b][d][n]
__device__ unsigned g_adjb[NTOK * (NTOK / 32)]; // adjacency bitmask (+self loops)

// ---------------- packed fp32x2 helpers (full-rate fp32 on sm_103a) ------
__device__ __forceinline__ ull pack2(float lo, float hi) {
    ull r;
    asm("mov.b64 %0, {%1, %2};" : "=l"(r) : "f"(lo), "f"(hi));
    return r;
}
__device__ __forceinline__ void unpack2(ull v, float& lo, float& hi) {
    asm("mov.b64 {%0, %1}, %2;" : "=f"(lo), "=f"(hi) : "l"(v));
}
__device__ __forceinline__ void fma2(ull& d, ull a, ull b) {
    asm("fma.rn.f32x2 %0, %1, %2, %0;" : "+l"(d) : "l"(a), "l"(b));
}
__device__ __forceinline__ void mul2(ull& d, ull s) {
    asm("mul.rn.f32x2 %0, %0, %1;" : "+l"(d) : "l"(s));
}
__device__ __forceinline__ float ex2f(float x) {
    float r;
    asm("ex2.approx.ftz.f32 %0, %1;" : "=f"(r) : "f"(x));
    return r;
}

// ---------------- cp.async helpers ---------------------------------------
__device__ __forceinline__ uint32_t s2u(const void* p) {
    return (uint32_t)__cvta_generic_to_shared(p);
}
__device__ __forceinline__ void cpa16(uint32_t dst, const void* src) {
    asm volatile("cp.async.cg.shared.global [%0], [%1], 16;\n" :: "r"(dst), "l"(src));
}
__device__ __forceinline__ void cp_commit() { asm volatile("cp.async.commit_group;\n"); }
template <int N> __device__ __forceinline__ void cp_wait() {
    asm volatile("cp.async.wait_group %0;\n" :: "n"(N));
}

// ---------------- adjacency bit-pack kernel (ballot) ---------------------
__global__ void pack_adj_kernel(const int* __restrict__ A) {
    int gtid = blockIdx.x * blockDim.x + threadIdx.x;
    int gw   = gtid >> 5;
    int lane = gtid & 31;
    int wb   = gw * 32;
    if (wb >= NTOK * (NTOK / 32)) return;
    int row   = wb >> 7;
    int wcol0 = wb & 127;
    const int* ap = A + (size_t)row * NTOK + wcol0 * 32;
    unsigned mine = 0u;
#pragma unroll 8
    for (int k = 0; k < 32; k++) {
        unsigned b = __ballot_sync(0xffffffffu, ap[k * 32 + lane] > 0);
        if (lane == k) mine = b;
    }
    if (wcol0 + lane == (row >> 5)) mine |= 1u << (row & 31);
    g_adjb[wb + lane] = mine;
}

// ---------------- projection kernel: v = X@W, q = X@Q, k = X@K -----------
#define XS_STR 68
#define PREP_SMEM_FLOATS (64 * XS_STR + 64 * 192)
#define PREP_SMEM_BYTES  (PREP_SMEM_FLOATS * 4)

__global__ __launch_bounds__(PT) void prep_kernel(
    const float* __restrict__ X, const float* __restrict__ W,
    const float* __restrict__ Q, const float* __restrict__ Kp)
{
    extern __shared__ float sm[];
    float* xs = sm;
    float* ws = sm + 64 * XS_STR;
    const int tid = threadIdx.x;
    const int g0  = blockIdx.x * 64;
    const int b   = g0 >> 12;
    const int n0  = g0 & (NTOK - 1);

    for (int idx = tid; idx < 64 * 16; idx += PT) {
        int r = idx >> 4, d4 = (idx & 15) << 2;
        float4 v = *(const float4*)(X + ((size_t)(g0 + r) << 6) + d4);
        xs[(d4 + 0) * XS_STR + r] = v.x;
        xs[(d4 + 1) * XS_STR + r] = v.y;
        xs[(d4 + 2) * XS_STR + r] = v.z;
        xs[(d4 + 3) * XS_STR + r] = v.w;
    }
    for (int idx = tid; idx < 64 * 48; idx += PT) {
        int d = idx / 48;
        int c4 = (idx % 48) << 2;
        const float* src;
        if (c4 < 64)       src = W  + d * 64 + c4;
        else if (c4 < 128) src = Q  + d * 64 + (c4 - 64);
        else               src = Kp + d * 64 + (c4 - 128);
        *(float4*)(ws + d * 192 + c4) = *(const float4*)src;
    }
    __syncthreads();

    const int cg = tid % 24, rg = tid / 24;
    float acc[8][8];
#pragma unroll
    for (int i = 0; i < 8; i++)
#pragma unroll
        for (int j = 0; j < 8; j++) acc[i][j] = 0.f;

#pragma unroll 4
    for (int d = 0; d < 64; d++) {
        float4 a0 = *(const float4*)(xs + d * XS_STR + (rg << 3));
        float4 a1 = *(const float4*)(xs + d * XS_STR + (rg << 3) + 4);
        float4 w0 = *(const float4*)(ws + d * 192 + (cg << 3));
        float4 w1 = *(const float4*)(ws + d * 192 + (cg << 3) + 4);
        float a[8] = {a0.x, a0.y, a0.z, a0.w, a1.x, a1.y, a1.z, a1.w};
        float w[8] = {w0.x, w0.y, w0.z, w0.w, w1.x, w1.y, w1.z, w1.w};
#pragma unroll
        for (int i = 0; i < 8; i++)
#pragma unroll
            for (int j = 0; j < 8; j++) acc[i][j] += a[i] * w[j];
    }

    if (cg < 8) {
#pragma unroll
        for (int i = 0; i < 8; i++) {
            float* dst = g_v + ((size_t)(g0 + (rg << 3) + i) << 6) + (cg << 3);
            *(float4*)(dst)     = make_float4(acc[i][0], acc[i][1], acc[i][2], acc[i][3]);
            *(float4*)(dst + 4) = make_float4(acc[i][4], acc[i][5], acc[i][6], acc[i][7]);
        }
    }

    __syncthreads();
    if (cg >= 8 && cg < 16) {
        int oc0 = (cg - 8) << 3;
#pragma unroll
        for (int j = 0; j < 8; j++)
#pragma unroll
            for (int i = 0; i < 8; i++)
                xs[(oc0 + j) * XS_STR + (rg << 3) + i] = acc[i][j];
    }
    __syncthreads();
    for (int idx = tid; idx < 4096; idx += PT) {
        int oc = idx >> 6, r = idx & 63;
        g_qt[((size_t)(b * 64 + oc) << 12) + n0 + r] = xs[oc * XS_STR + r];
    }
    __syncthreads();
    if (cg >= 16) {
        int oc0 = (cg - 16) << 3;
#pragma unroll
        for (int j = 0; j < 8; j++)
#pragma unroll
            for (int i = 0; i < 8; i++)
                xs[(oc0 + j) * XS_STR + (rg << 3) + i] = acc[i][j];
    }
    __syncthreads();
    for (int idx = tid; idx < 4096; idx += PT) {
        int oc = idx >> 6, r = idx & 63;
        g_kt[((size_t)(b * 64 + oc) << 12) + n0 + r] = xs[oc * XS_STR + r];
    }
}

// ---------------- fused flash-attention GAT kernel -----------------------
// cp.async phase-shifted pipeline: k[kt+1] prefetched during softmax+PV,
// v[kt] prefetched during QK, adjacency in registers.
// ks/vs chunk-swizzled (ch ^ ((ch>>3)&1)) -> conflict-free 8-chunk row reads.
#define QS_OFF 0
#define KS_OFF 8192
#define VS_OFF 12288
#define PS_OFF 16384
#define PS_STR 68
#define ATTN_SMEM_FLOATS (PS_OFF + 128 * PS_STR)
#define ATTN_SMEM_BYTES  (ATTN_SMEM_FLOATS * 4)   // 100352

__global__ __launch_bounds__(AT, 2) void attn_kernel(float* __restrict__ out) {
    extern __shared__ float sm[];
    float* qs = sm + QS_OFF;   // [d][r]  64 x 128
    float* ks = sm + KS_OFF;   // [d][c]  64 x 64, chunk-swizzled
    float* vs = sm + VS_OFF;   // [j][oc] 64 x 64, chunk-swizzled
    float* ps = sm + PS_OFF;   // [row][col] 128 x 68, chunk-swizzled by sw

    const int tid = threadIdx.x;
    const int q0  = blockIdx.x * BM;
    const int b   = blockIdx.y;
    const int rg  = tid >> 3;   // 8 query rows each
    const int cg  = tid & 7;    // 8 key/out cols each
    const int sw  = (rg & 3) << 1;
    const int ca  = cg << 1, cbk = ca + 1;
    const int kaoff = (ca  ^ ((ca  >> 3) & 1)) << 2;  // float offsets into 16-chunk rows
    const int kboff = (cbk ^ ((cbk >> 3) & 1)) << 2;

    const float* qtb = g_qt + ((size_t)b << 18);
    const float* ktb = g_kt + ((size_t)b << 18);
    const float* vb  = g_v  + ((size_t)b << 18);
    const unsigned* adjp = g_adjb + (((size_t)(q0 + (rg << 3))) << 7) + (cg >> 2);

    // prologue: q tile + k[0] as one cp.async group
    for (int idx = tid; idx < 2048; idx += AT) {
        int d = idx >> 5, ch = idx & 31;
        cpa16(s2u(qs + d * BM + (ch << 2)),
              qtb + ((size_t)d << 12) + q0 + (ch << 2));
    }
    for (int idx = tid; idx < 1024; idx += AT) {
        int d = idx >> 4, ch = idx & 15;
        cpa16(s2u(ks + d * BN + ((ch ^ ((ch >> 3) & 1)) << 2)),
              ktb + ((size_t)d << 12) + (ch << 2));
    }
    cp_commit();

    ull O2[8][4];
    float m[8], l[8];
#pragma unroll
    for (int i = 0; i < 8; i++) {
        m[i] = -INFINITY; l[i] = 0.f;
#pragma unroll
        for (int jp = 0; jp < 4; jp++) O2[i][jp] = 0ull;
    }

    const float L2E = 1.4426950408889634f;

    for (int kt = 0; kt < KITER; kt++) {
        const int k0 = kt * BN;
        __syncthreads();                       // A: prev PV done with vs/ps
        // B: prefetch v[kt]
        for (int idx = tid; idx < 1024; idx += AT) {
            int r = idx >> 4, ch = idx & 15;
            cpa16(s2u(vs + r * DIM + ((ch ^ ((ch >> 3) & 1)) << 2)),
                  vb + ((size_t)(k0 + r) << 6) + (ch << 2));
        }
        cp_commit();
        // adjacency words for this tile -> registers
        unsigned aw[8];
#pragma unroll
        for (int i = 0; i < 8; i++) aw[i] = __ldg(adjp + i * 128 + (kt << 1));

        cp_wait<1>();                          // C: k[kt] (+q on kt=0) resident
        __syncthreads();                       // D: publish ks (and qs)

        // ---- S = q . k^T ----
        ull acc[8][4];
#pragma unroll
        for (int i = 0; i < 8; i++)
#pragma unroll
            for (int jp = 0; jp < 4; jp++) acc[i][jp] = 0ull;

#pragma unroll 4
        for (int d = 0; d < DIM; d++) {
            const float* qrow = qs + d * BM + (rg << 3);
            float4 qa = *(const float4*)(qrow);
            float4 qb = *(const float4*)(qrow + 4);
            const float* krow = ks + d * BN;
            ulonglong2 ka = *(const ulonglong2*)(krow + kaoff);
            ulonglong2 kb = *(const ulonglong2*)(krow + kboff);
            float qv[8] = {qa.x, qa.y, qa.z, qa.w, qb.x, qb.y, qb.z, qb.w};
#pragma unroll
            for (int i = 0; i < 8; i++) {
                ull aq = pack2(qv[i], qv[i]);
                fma2(acc[i][0], aq, ka.x);
                fma2(acc[i][1], aq, ka.y);
                fma2(acc[i][2], aq, kb.x);
                fma2(acc[i][3], aq, kb.y);
            }
        }
        __syncthreads();                       // F: done reading ks

        // G: prefetch k[kt+1] (skip on last iter; commit always for FIFO parity)
        if (kt + 1 < KITER) {
            const int kn = k0 + BN;
            for (int idx = tid; idx < 1024; idx += AT) {
                int d = idx >> 4, ch = idx & 15;
                cpa16(s2u(ks + d * BN + ((ch ^ ((ch >> 3) & 1)) << 2)),
                      ktb + ((size_t)d << 12) + kn + (ch << 2));
            }
        }
        cp_commit();

        // ---- H: leaky relu + mask + online softmax; store P row-major ----
#pragma unroll
        for (int i = 0; i < 8; i++) {
            const int row = (rg << 3) + i;
            float s[8];
            unpack2(acc[i][0], s[0], s[1]);
            unpack2(acc[i][1], s[2], s[3]);
            unpack2(acc[i][2], s[4], s[5]);
            unpack2(acc[i][3], s[6], s[7]);
#pragma unroll
            for (int j = 0; j < 8; j++) s[j] = s[j] > 0.f ? s[j] : 0.01f * s[j];

            unsigned w = aw[i];
            const int cb2 = (cg & 3) << 3;
            bool val[8];
            float mloc = -INFINITY;
#pragma unroll
            for (int j = 0; j < 8; j++) {
                val[j] = (w >> (cb2 + j)) & 1u;
                mloc = fmaxf(mloc, val[j] ? s[j] : -INFINITY);
            }
            mloc = fmaxf(mloc, __shfl_xor_sync(0xffffffffu, mloc, 1));
            mloc = fmaxf(mloc, __shfl_xor_sync(0xffffffffu, mloc, 2));
            mloc = fmaxf(mloc, __shfl_xor_sync(0xffffffffu, mloc, 4));

            float mnew = fmaxf(m[i], mloc);
            float sc = (mnew == -INFINITY) ? 0.f : ex2f((m[i] - mnew) * L2E);
            float mb = mnew * L2E;
            float p[8];
            float rs = 0.f;
#pragma unroll
            for (int j = 0; j < 8; j++) {
                p[j] = val[j] ? ex2f(fmaf(s[j], L2E, -mb)) : 0.f;
                rs += p[j];
            }
            rs += __shfl_xor_sync(0xffffffffu, rs, 1);
            rs += __shfl_xor_sync(0xffffffffu, rs, 2);
            rs += __shfl_xor_sync(0xffffffffu, rs, 4);
            l[i] = l[i] * sc + rs;
            m[i] = mnew;
            ull sc2 = pack2(sc, sc);
#pragma unroll
            for (int jp = 0; jp < 4; jp++) mul2(O2[i][jp], sc2);

            float* base = ps + row * PS_STR;
            *(float4*)(base + ((((cg << 1))     ^ sw) << 2)) = make_float4(p[0], p[1], p[2], p[3]);
            *(float4*)(base + ((((cg << 1) + 1) ^ sw) << 2)) = make_float4(p[4], p[5], p[6], p[7]);
        }

        cp_wait<1>();                          // I: v[kt] resident
        __syncthreads();                       // J: publish vs + ps

        // ---- O += P @ V ----
#pragma unroll 2
        for (int jb = 0; jb < 16; jb++) {
            float pr[8][4];
#pragma unroll
            for (int i = 0; i < 8; i++) {
                const int row = (rg << 3) + i;
                float4 t = *(const float4*)(ps + row * PS_STR + ((jb ^ sw) << 2));
                pr[i][0] = t.x; pr[i][1] = t.y; pr[i][2] = t.z; pr[i][3] = t.w;
            }
#pragma unroll
            for (int jj = 0; jj < 4; jj++) {
                const int j = (jb << 2) + jj;
                const float* vrow = vs + j * DIM;
                ulonglong2 va  = *(const ulonglong2*)(vrow + kaoff);
                ulonglong2 vbb = *(const ulonglong2*)(vrow + kboff);
#pragma unroll
                for (int i = 0; i < 8; i++) {
                    ull pd = pack2(pr[i][jj], pr[i][jj]);
                    fma2(O2[i][0], pd, va.x);
                    fma2(O2[i][1], pd, va.y);
                    fma2(O2[i][2], pd, vbb.x);
                    fma2(O2[i][3], pd, vbb.y);
                }
            }
        }
    }

    // ---- normalize + store ----
#pragma unroll
    for (int i = 0; i < 8; i++) {
        float inv = 1.0f / l[i];
        ull iv = pack2(inv, inv);
#pragma unroll
        for (int jp = 0; jp < 4; jp++) mul2(O2[i][jp], iv);
        float o[8];
        unpack2(O2[i][0], o[0], o[1]);
        unpack2(O2[i][1], o[2], o[3]);
        unpack2(O2[i][2], o[4], o[5]);
        unpack2(O2[i][3], o[6], o[7]);
        float* dst = out + ((size_t)(b * NTOK + q0 + (rg << 3) + i) << 6) + (cg << 3);
        *(float4*)(dst)     = make_float4(o[0], o[1], o[2], o[3]);
        *(float4*)(dst + 4) = make_float4(o[4], o[5], o[6], o[7]);
    }
}

// ---------------- launch ----------------
extern "C" void kernel_launch(void* const* d_in, const int* in_sizes, int n_in,
                              void* d_out, int out_size) {
    const float* X  = (const float*)d_in[0];
    const int*   A  = (const int*)  d_in[1];
    const float* W  = (const float*)d_in[2];
    const float* Q  = (const float*)d_in[3];
    const float* Kp = (const float*)d_in[4];
    float* out = (float*)d_out;

    cudaFuncSetAttribute(prep_kernel, cudaFuncAttributeMaxDynamicSharedMemorySize, PREP_SMEM_BYTES);
    cudaFuncSetAttribute(attn_kernel, cudaFuncAttributeMaxDynamicSharedMemorySize, ATTN_SMEM_BYTES);

    pack_adj_kernel<<<(NTOK * (NTOK / 32)) / 256, 256>>>(A);
    prep_kernel<<<(BATCH * NTOK) / 64, PT, PREP_SMEM_BYTES>>>(X, W, Q, Kp);
    attn_kernel<<<dim3(NTOK / BM, BATCH), AT, ATTN_SMEM_BYTES>>>(out);
}